// round 17
// baseline (speedup 1.0000x reference)
#include <cuda_runtime.h>
#include <cuda_fp16.h>

#define K_CAPS 10
#define B_SZ   256
#define N_IN   1152
#define IC     8
#define OC     16

// fp16 scratch for u_hat: 10*256*1152*16 halves = 94.4 MB, layout [k][b][n][o]
__device__ __half2 g_uhat[(size_t)K_CAPS * B_SZ * N_IN * OC / 2];
// per-k completion counters for the in-kernel uhat->routing pipeline
__device__ unsigned int g_done[K_CAPS];

// ---- packed f32x2 helpers (sm_103a FFMA2 path, PTX-only) -------------------
__device__ __forceinline__ unsigned long long pk2(float lo, float hi) {
    unsigned long long r;
    asm("mov.b64 %0, {%1, %2};" : "=l"(r) : "f"(lo), "f"(hi));
    return r;
}
__device__ __forceinline__ unsigned long long fma2(unsigned long long a,
                                                   unsigned long long b,
                                                   unsigned long long c) {
    unsigned long long d;
    asm("fma.rn.f32x2 %0, %1, %2, %3;" : "=l"(d) : "l"(a), "l"(b), "l"(c));
    return d;
}
__device__ __forceinline__ float2 unpk2(unsigned long long v) {
    float2 f;
    asm("mov.b64 {%0, %1}, %2;" : "=f"(f.x), "=f"(f.y) : "l"(v));
    return f;
}

// ---------------------------------------------------------------------------
// Pre-kernel: reset per-k pipeline counters each launch / graph replay.
// ---------------------------------------------------------------------------
__global__ void zero_kernel() {
    if (threadIdx.x < K_CAPS) g_done[threadIdx.x] = 0u;
}

// ---------------------------------------------------------------------------
// Fused kernel: per-k interleaved [32 uhat blocks | 256 routing blocks].
// Memory protocol (fixed vs R16):
//   producer: STG ... ; __threadfence() PER THREAD ; __syncthreads() ;
//             t0 atomicAdd(g_done[k])            (proper release)
//   consumer: t0 spins on volatile g_done[k]==32 ; __threadfence() ;
//             __syncthreads() ; plain LDG (NOT __ldg -- data is written
//             this kernel, the .nc path is illegal for it)
// Block order guarantees uhat-k blocks precede routing-k blocks in dispatch,
// so spinners cannot starve the producers.
// ---------------------------------------------------------------------------
#define UHAT_BLKS_PER_K 32            // 4 b-tiles x 8 n-tiles
#define BLKS_PER_K      (UHAT_BLKS_PER_K + B_SZ)   // 288

__global__ __launch_bounds__(576, 2) void fused_kernel(const float* __restrict__ u,
                                                       const float* __restrict__ W,
                                                       float* __restrict__ out) {
    const int k = blockIdx.x / BLKS_PER_K;
    const int j = blockIdx.x % BLKS_PER_K;
    const int t = threadIdx.x;

    __shared__ float sj[18][20];      // routing: [warp][o(0..15), esum]
    __shared__ float sv[16];          // routing: v_j broadcast

    if (j < UHAT_BLKS_PER_K) {
        // ================= uhat role =================
        const int btile = j >> 3;
        const int ntile = j & 7;
        const int q  = t & 3;
        const int nl = t >> 2;                    // 0..143
        const int n  = ntile * 144 + nl;
        const int b0 = btile * 64;

        const float4* Wv = reinterpret_cast<const float4*>(
            W + ((size_t)k * N_IN + n) * (IC * OC)) + q;
        unsigned long long w01[8], w23[8];
#pragma unroll
        for (int i = 0; i < 8; i++) {
            const float4 wv = __ldg(Wv + i * 4);  // W is truly read-only: ok
            w01[i] = pk2(wv.x, wv.y);
            w23[i] = pk2(wv.z, wv.w);
        }

        const float4* uv   = reinterpret_cast<const float4*>(u);
        uint2*        outv = reinterpret_cast<uint2*>(g_uhat);

#pragma unroll 2
        for (int bb = 0; bb < 64; bb++) {
            const int b = b0 + bb;
            const size_t ui = ((size_t)b * N_IN + n) * 2;
            const float4 ua = __ldg(uv + ui);     // u read-only: ok
            const float4 ub = __ldg(uv + ui + 1);
            const float uu[8] = {ua.x, ua.y, ua.z, ua.w, ub.x, ub.y, ub.z, ub.w};

            unsigned long long a01 = 0ull, a23 = 0ull;
#pragma unroll
            for (int i = 0; i < 8; i++) {
                const unsigned long long up = pk2(uu[i], uu[i]);
                a01 = fma2(up, w01[i], a01);
                a23 = fma2(up, w23[i], a23);
            }
            const float2 f01 = unpk2(a01);
            const float2 f23 = unpk2(a23);
            const __half2 h0 = __float22half2_rn(f01);
            const __half2 h1 = __float22half2_rn(f23);
            uint2 pk;
            pk.x = *reinterpret_cast<const unsigned int*>(&h0);
            pk.y = *reinterpret_cast<const unsigned int*>(&h1);
            outv[(((size_t)k * B_SZ + b) * N_IN + n) * 4 + q] = pk;
        }

        __threadfence();                          // EACH thread: release its stores
        __syncthreads();                          // all fences done block-wide
        if (t == 0) atomicAdd(&g_done[k], 1u);    // signal
        return;
    }

    // ================= routing role =================
    const int b  = j - UHAT_BLKS_PER_K;
    const int kb = k * B_SZ + b;

    // wait for this k's uhat slice
    if (t == 0) {
        volatile unsigned int* p = &g_done[k];
        while (*p < UHAT_BLKS_PER_K) __nanosleep(200);
        __threadfence();                          // acquire
    }
    __syncthreads();

    const uint2* uh = reinterpret_cast<const uint2*>(g_uhat)
                      + (size_t)kb * (N_IN * 4);
    const int wid  = t >> 5;
    const int lane = t & 31;
    const int q    = lane & 3;       // o-quad: columns 4q..4q+3
    const int rsub = lane >> 2;      // row within 8-row group

    // ---- one-time load (PLAIN LDG: g_uhat is written this kernel), widen,
    //      PIN fp32 so ptxas cannot rematerialize the conversions ----
    float4 r[8];
#pragma unroll
    for (int s = 0; s < 8; s++) {
        const int n = 8 * (wid * 8 + s) + rsub;
        const uint2 v = uh[n * 4 + q];            // coherent LDG.E.64
        const __half2 h0 = *reinterpret_cast<const __half2*>(&v.x);
        const __half2 h1 = *reinterpret_cast<const __half2*>(&v.y);
        const float2 f0 = __half22float2(h0);
        const float2 f1 = __half22float2(h1);
        r[s] = make_float4(f0.x, f0.y, f1.x, f1.y);
        asm volatile("" : "+f"(r[s].x), "+f"(r[s].y), "+f"(r[s].z), "+f"(r[s].w));
    }
    float blog[8];
#pragma unroll
    for (int s = 0; s < 8; s++) blog[s] = 0.f;

    for (int it = 0; it < 3; it++) {
        // ---- fused (a + s) sweep over this thread's 8 rows ----
        float4 acc = make_float4(0.f, 0.f, 0.f, 0.f);
        float esum = 0.f;
        if (it == 0) {
#pragma unroll
            for (int s = 0; s < 8; s++) {
                acc.x += r[s].x; acc.y += r[s].y;
                acc.z += r[s].z; acc.w += r[s].w;
            }
        } else {
            const float4 vq = reinterpret_cast<const float4*>(sv)[q];
#pragma unroll
            for (int s = 0; s < 8; s++) {
                float d = r[s].x * vq.x;
                d = fmaf(r[s].y, vq.y, d);
                d = fmaf(r[s].z, vq.z, d);
                d = fmaf(r[s].w, vq.w, d);
                // full row dot: sum over the 4 q-lanes (bit-identical on all 4)
                d += __shfl_xor_sync(0xffffffffu, d, 1);
                d += __shfl_xor_sync(0xffffffffu, d, 2);
                blog[s] += d;
                const float w = __expf(blog[s]);      // no max-sub: |blog|<=~40
                esum += (q == 0) ? w : 0.f;           // count each row once
                acc.x = fmaf(w, r[s].x, acc.x);
                acc.y = fmaf(w, r[s].y, acc.y);
                acc.z = fmaf(w, r[s].z, acc.z);
                acc.w = fmaf(w, r[s].w, acc.w);
            }
        }
        // reduce over lanes sharing the same q (offsets 4,8,16); esum rides along
#pragma unroll
        for (int off = 4; off <= 16; off <<= 1) {
            acc.x += __shfl_xor_sync(0xffffffffu, acc.x, off);
            acc.y += __shfl_xor_sync(0xffffffffu, acc.y, off);
            acc.z += __shfl_xor_sync(0xffffffffu, acc.z, off);
            acc.w += __shfl_xor_sync(0xffffffffu, acc.w, off);
            esum  += __shfl_xor_sync(0xffffffffu, esum,  off);
        }
        if (lane < 4) {                       // lanes 0..3 hold o = 4q..4q+3
            sj[wid][4 * q + 0] = acc.x;
            sj[wid][4 * q + 1] = acc.y;
            sj[wid][4 * q + 2] = acc.z;
            sj[wid][4 * q + 3] = acc.w;
        }
        if (lane == 0) sj[wid][16] = esum;
        __syncthreads();

        // ---- warp 0: cross-warp reduce (17 values x 18 warps), squash ----
        if (wid == 0) {
            float val = 0.f;
            if (lane < 17) {
#pragma unroll
                for (int ww = 0; ww < 18; ww++) val += sj[ww][lane];
            }
            const float Z = __shfl_sync(0xffffffffu, val, 16);
            const float invZ = (it == 0) ? (1.f / (float)N_IN) : (1.f / Z);
            float s_ = (lane < 16) ? val * invZ : 0.f;
            float sq = s_ * s_;
#pragma unroll
            for (int off = 8; off; off >>= 1)
                sq += __shfl_xor_sync(0xffffffffu, sq, off);
            const float scale = sqrtf(sq) / (1.f + sq);   // squash factor
            const float v = s_ * scale;
            if (lane < 16) {
                if (it == 2) out[(size_t)kb * OC + lane] = v;
                else         sv[lane] = v;
            }
        }
        __syncthreads();
    }
}

// ---------------------------------------------------------------------------
extern "C" void kernel_launch(void* const* d_in, const int* in_sizes, int n_in,
                              void* d_out, int out_size) {
    const float* u = (const float*)d_in[0];
    const float* W = (const float*)d_in[1];
    if (in_sizes[0] == K_CAPS * N_IN * IC * OC) {   // robust to input ordering
        W = (const float*)d_in[0];
        u = (const float*)d_in[1];
    }
    zero_kernel<<<1, 32>>>();
    fused_kernel<<<K_CAPS * BLKS_PER_K, 576>>>(u, W, (float*)d_out);
}